// round 4
// baseline (speedup 1.0000x reference)
#include <cuda_runtime.h>

#define C_  512
#define Hh  24
#define Ww  24
#define HW  576
#define NH  8
#define HD  64
#define PW  30
#define PP  900
#define KP  1024          /* padded distinct-key count */
#define SEW 1028          /* sE row stride (4-float pad) */

typedef unsigned long long ull;

// Scratch (device globals: allocation-free)
__device__ float g_Xp[C_ * KP];   // reflect-padded x; zeros for pp>=900
__device__ float g_Q [C_ * HW];   // Q[o][p]
__device__ float g_K [C_ * KP];   // K[o][pp]
__device__ float g_VT[KP * C_];   // V transposed: VT[pp][o]

// ---- packed fp32x2 helpers ----
__device__ __forceinline__ void fma2(ull &d, ull a, ull b) {
    asm("fma.rn.f32x2 %0, %1, %2, %0;" : "+l"(d) : "l"(a), "l"(b));
}
__device__ __forceinline__ float2 upk(ull v) {
    float2 r; asm("mov.b64 {%0, %1}, %2;" : "=f"(r.x), "=f"(r.y) : "l"(v)); return r;
}

// ---------------------------------------------------------------------------
// Kernel 1: reflect-pad gather. g_Xp[c][pp] (pp = pr*30+pc), zeros for pp>=900.
// ---------------------------------------------------------------------------
__global__ void pad_kernel(const float* __restrict__ x) {
    int idx = blockIdx.x * 256 + threadIdx.x;
    int c = idx >> 10, pp = idx & (KP - 1);
    float v = 0.f;
    if (pp < PP) {
        int pr = pp / PW, pc = pp - pr * PW;
        int r = pr - 3; r = (r < 0) ? -r : ((r >= Hh) ? 2 * Hh - 2 - r : r);
        int cl = pc - 3; cl = (cl < 0) ? -cl : ((cl >= Ww) ? 2 * Ww - 2 - cl : cl);
        v = x[c * HW + r * Ww + cl];
    }
    g_Xp[idx] = v;
}

// ---------------------------------------------------------------------------
// Kernel 2 (fused): all three conv1x1 GEMMs, 328 CTAs.
//   bid [0,72)   : Q  = Wq @ x      (N=576)
//   bid [72,200) : K  = Wk @ Xp     (N=1024)
//   bid [200,328): VT = (Wv @ Xp)^T (N=1024, transposed store via smem)
// 64x64 tile, 256 threads, 4x4 micro-tile, double-buffered smem.
// A stored DUPLICATED in smem -> splat operand is a single LDS.64.
// Inner t-step: 4 LDS.64 + 1 LDS.128 + 8 FFMA2 = 13 issues / 16 fma-pipe cyc.
// ---------------------------------------------------------------------------
__global__ void __launch_bounds__(256) gemm_all_kernel(
    const float* __restrict__ Wq, const float* __restrict__ bq,
    const float* __restrict__ Wk, const float* __restrict__ bk,
    const float* __restrict__ Wv, const float* __restrict__ bv,
    const float* __restrict__ x)
{
    __shared__ float sm[6272];  // sA0@0[2112] sA1@2112[2112] sB0@4224[1024] sB1@5248[1024]

    int bid = blockIdx.x;
    const float *Wm, *bias, *X; float* Cout; int N, transp = 0, nt, ot;
    if (bid < 72)       { nt = bid % 9;      ot = bid / 9;  Wm = Wq; bias = bq; X = x;    Cout = g_Q;  N = HW; }
    else if (bid < 200) { int b = bid - 72;  nt = b & 15; ot = b >> 4; Wm = Wk; bias = bk; X = g_Xp; Cout = g_K;  N = KP; }
    else                { int b = bid - 200; nt = b & 15; ot = b >> 4; Wm = Wv; bias = bv; X = g_Xp; Cout = g_VT; N = KP; transp = 1; }
    int nB = nt * 64, oB = ot * 64;

    int tid = threadIdx.x;
    int tj = tid & 15, ti = tid >> 4;            // micro-tile: 4 o-rows (4ti), 4 n-cols (4tj)
    int aoo = tid >> 2, acg = (tid & 3) << 2;    // A stage: o-row 0..63, c-group of 4
    int bl = tid >> 4, bn = (tid & 15) << 2;     // B stage: c-row 0..15, n-group of 4

    float* sA[2] = { sm,        sm + 2112 };     // [c][2*o] duplicated, stride 132
    float* sB[2] = { sm + 4224, sm + 5248 };     // [c][n], stride 64

    ull acc[4][2];
#pragma unroll
    for (int i = 0; i < 4; i++) { acc[i][0] = 0ULL; acc[i][1] = 0ULL; }

    // preload chunk 0
    {
        float4 w4 = *(const float4*)&Wm[(oB + aoo) * C_ + acg];
        float4 x4 = *(const float4*)&X[bl * N + nB + bn];
        float wv[4] = {w4.x, w4.y, w4.z, w4.w};
#pragma unroll
        for (int j = 0; j < 4; j++)
            *(float2*)&sA[0][(acg + j) * 132 + 2 * aoo] = make_float2(wv[j], wv[j]);
        *(float4*)&sB[0][bl * 64 + bn] = x4;
    }
    __syncthreads();

    for (int cc = 0; cc < C_; cc += 16) {
        int cur = (cc >> 4) & 1;
        const float* cA = sA[cur];
        const float* cB = sB[cur];
        bool pf = cc + 16 < C_;
        float4 w4n, x4n;
        if (pf) {
            w4n = *(const float4*)&Wm[(oB + aoo) * C_ + cc + 16 + acg];
            x4n = *(const float4*)&X[(cc + 16 + bl) * N + nB + bn];
        }
#pragma unroll
        for (int t = 0; t < 16; t++) {
            ulonglong2 b2 = *(const ulonglong2*)&cB[t * 64 + (tj << 2)];
            const float* ab = &cA[t * 132 + (ti << 3)];
            ull a0 = *(const ull*)&ab[0];
            ull a1 = *(const ull*)&ab[2];
            ull a2 = *(const ull*)&ab[4];
            ull a3 = *(const ull*)&ab[6];
            fma2(acc[0][0], a0, b2.x); fma2(acc[0][1], a0, b2.y);
            fma2(acc[1][0], a1, b2.x); fma2(acc[1][1], a1, b2.y);
            fma2(acc[2][0], a2, b2.x); fma2(acc[2][1], a2, b2.y);
            fma2(acc[3][0], a3, b2.x); fma2(acc[3][1], a3, b2.y);
        }
        if (pf) {
            float* nA = sA[cur ^ 1];
            float* nBp = sB[cur ^ 1];
            float wv[4] = {w4n.x, w4n.y, w4n.z, w4n.w};
#pragma unroll
            for (int j = 0; j < 4; j++)
                *(float2*)&nA[(acg + j) * 132 + 2 * aoo] = make_float2(wv[j], wv[j]);
            *(float4*)&nBp[bl * 64 + bn] = x4n;
        }
        __syncthreads();
    }

    // epilogue
    float4 cv[4];
#pragma unroll
    for (int i = 0; i < 4; i++) {
        float bv_ = bias[oB + (ti << 2) + i];
        float2 c01 = upk(acc[i][0]), c23 = upk(acc[i][1]);
        cv[i] = make_float4(c01.x + bv_, c01.y + bv_, c23.x + bv_, c23.y + bv_);
    }
    if (!transp) {
#pragma unroll
        for (int i = 0; i < 4; i++)
            *(float4*)&Cout[(oB + (ti << 2) + i) * N + nB + (tj << 2)] = cv[i];
    } else {
        // transpose through smem for coalesced VT stores
        float* sT = sm;                          // [n][o], 64 x 65 = 4160 <= 6272
#pragma unroll
        for (int i = 0; i < 4; i++) {
            sT[((tj << 2) + 0) * 65 + (ti << 2) + i] = cv[i].x;
            sT[((tj << 2) + 1) * 65 + (ti << 2) + i] = cv[i].y;
            sT[((tj << 2) + 2) * 65 + (ti << 2) + i] = cv[i].z;
            sT[((tj << 2) + 3) * 65 + (ti << 2) + i] = cv[i].w;
        }
        __syncthreads();
#pragma unroll
        for (int it = 0; it < 16; it++) {
            int idx = it * 256 + tid;
            int n = idx >> 6, o = idx & 63;
            Cout[(nB + n) * C_ + oB + o] = sT[n * 65 + o];
        }
    }
}

// ---------------------------------------------------------------------------
// Kernel 3: fused attention, 1024 padded dedup keys, weighted softmax.
// Grid (36 qtiles, 8 heads) = 288 CTAs x 256 threads, 16-query tiles.
// smem 108.9KB -> 2 CTAs/SM, one wave. Single K/V smem buffer with
// REGISTER double-buffering (prefetch next chunk to regs during compute).
// ---------------------------------------------------------------------------
__global__ void __launch_bounds__(256) attn_kernel(const float* __restrict__ x,
                            const float* __restrict__ gamma_p,
                            float* __restrict__ out) {
    extern __shared__ float smd[];
    float* sQd  = smd;                     // [64][32]: Q duplicated pairs, 2048
    float* sKV  = smd + 2048;              // 8704: pass1 K [64][136]; pass2 V [128][68]
    float* sE   = smd + 2048 + 8704;       // 16*1028 = 16448
    float* sInv = sE + 16 * SEW;           // 16
    // total 27216 floats = 108864 B

    int h   = blockIdx.y;
    int q0  = blockIdx.x * 16;
    int tid = threadIdx.x;

    // ---- Load Q tile, store DUPLICATED: sQd[d][2q..2q+1] = Q[d][q] ----
    {
        int d = tid >> 2, qg = (tid & 3) << 2;
        float4 q4 = *(const float4*)&g_Q[(h * HD + d) * HW + q0 + qg];
        float qv[4] = {q4.x, q4.y, q4.z, q4.w};
#pragma unroll
        for (int j = 0; j < 4; j++)
            *(float2*)&sQd[d * 32 + 2 * (qg + j)] = make_float2(qv[j], qv[j]);
    }
    // ---- preload K chunk 0 to regs, then smem: sK[64][136] ----
    int kd = tid >> 2, kg = (tid & 3) << 5;        // K stage: row d, 32-float group
    float4 kr[8];
    {
        const float4* src = (const float4*)&g_K[(h * HD + kd) * KP + kg];
#pragma unroll
        for (int j = 0; j < 8; j++) kr[j] = src[j];
        float4* dst = (float4*)&sKV[kd * 136 + kg];
#pragma unroll
        for (int j = 0; j < 8; j++) dst[j] = kr[j];
    }
    __syncthreads();

    // ---- Pass 1: E[q][k] = sum_d Q[d][q]*K[d][k]. 2q x 4k micro, 128-key chunks ----
    {
        int tx = tid & 31, ty = tid >> 5;          // k-quad 4tx, q-pair 2ty
        for (int kc = 0; kc < KP; kc += 128) {
            bool pf = kc + 128 < KP;
            if (pf) {
                const float4* src = (const float4*)&g_K[(h * HD + kd) * KP + kc + 128 + kg];
#pragma unroll
                for (int j = 0; j < 8; j++) kr[j] = src[j];
            }
            ull e00 = 0, e01 = 0, e10 = 0, e11 = 0;
#pragma unroll 16
            for (int d = 0; d < 64; d++) {
                ull a0 = *(const ull*)&sQd[d * 32 + (ty << 2)];
                ull a1 = *(const ull*)&sQd[d * 32 + (ty << 2) + 2];
                ulonglong2 b = *(const ulonglong2*)&sKV[d * 136 + (tx << 2)];
                fma2(e00, a0, b.x); fma2(e01, a0, b.y);
                fma2(e10, a1, b.x); fma2(e11, a1, b.y);
            }
            {
                float2 p0 = upk(e00), p1 = upk(e01), p2 = upk(e10), p3 = upk(e11);
                int r = (ty << 1) * SEW + kc + (tx << 2);
                *(float4*)&sE[r]       = make_float4(p0.x, p0.y, p1.x, p1.y);
                *(float4*)&sE[r + SEW] = make_float4(p2.x, p2.y, p3.x, p3.y);
            }
            __syncthreads();
            if (pf) {
                float4* dst = (float4*)&sKV[kd * 136 + kg];
#pragma unroll
                for (int j = 0; j < 8; j++) dst[j] = kr[j];
            }
            __syncthreads();
        }
    }

    // ---- prefetch V chunk 0 (completes under softmax): sV[128][68] ----
    int vk = tid >> 1, vg = (tid & 1) << 5;        // V stage: row k, 32-float group
    float4 vr[8];
    {
        const float4* src = (const float4*)&g_VT[vk * C_ + h * HD + vg];
#pragma unroll
        for (int j = 0; j < 8; j++) vr[j] = src[j];
    }

    // ---- Multiplicity-weighted softmax in place (interleaved, conflict-free) ----
    {
        int row = tid >> 4, part = tid & 15;       // 16 threads per query row
        float* Er = &sE[row * SEW];
        float m = -1e30f;
#pragma unroll 8
        for (int j = 0; j < 64; j++) m = fmaxf(m, Er[part + (j << 4)]);
        m = fmaxf(m, __shfl_xor_sync(~0u, m, 1));
        m = fmaxf(m, __shfl_xor_sync(~0u, m, 2));
        m = fmaxf(m, __shfl_xor_sync(~0u, m, 4));
        m = fmaxf(m, __shfl_xor_sync(~0u, m, 8));
        float s = 0.f;
        for (int j = 0; j < 64; j++) {
            int i = part + (j << 4);
            float w = 0.f;
            if (i < PP) {
                int pr = i / PW, pc = i - pr * PW;
                int mr = min(pr + 1, min(7, PW - pr));
                int mc = min(pc + 1, min(7, PW - pc));
                w = (float)(mr * mc);
            }
            float p = w * __expf(Er[i] - m);
            Er[i] = p;
            s += p;
        }
        s += __shfl_xor_sync(~0u, s, 1);
        s += __shfl_xor_sync(~0u, s, 2);
        s += __shfl_xor_sync(~0u, s, 4);
        s += __shfl_xor_sync(~0u, s, 8);
        if (part == 0) sInv[row] = 1.f / s;
    }
    __syncthreads();           // pass1 reads of sKV done; E finalized
    {
        float4* dst = (float4*)&sKV[vk * 68 + vg];
#pragma unroll
        for (int j = 0; j < 8; j++) dst[j] = vr[j];
    }
    __syncthreads();

    // ---- Pass 2: out[q][d] = sum_k P[q][k]*V[k][d]. SCALAR FFMA, 1q x 4d ----
    float o0 = 0.f, o1 = 0.f, o2 = 0.f, o3 = 0.f;
    {
        int tx = tid & 15, ty = tid >> 4;          // d-quad 4tx, q = ty
        for (int kc = 0; kc < KP; kc += 128) {
            bool pf = kc + 128 < KP;
            if (pf) {
                const float4* src = (const float4*)&g_VT[(kc + 128 + vk) * C_ + h * HD + vg];
#pragma unroll
                for (int j = 0; j < 8; j++) vr[j] = src[j];
            }
            const float* Pr = &sE[ty * SEW + kc];
#pragma unroll 8
            for (int k = 0; k < 128; k++) {
                float p = Pr[k];
                float4 v = *(const float4*)&sKV[k * 68 + (tx << 2)];
                o0 += p * v.x; o1 += p * v.y; o2 += p * v.z; o3 += p * v.w;
            }
            __syncthreads();
            if (pf) {
                float4* dst = (float4*)&sKV[vk * 68 + vg];
#pragma unroll
                for (int j = 0; j < 8; j++) dst[j] = vr[j];
            }
            __syncthreads();
        }
    }

    // ---- Epilogue via smem transpose: out = gamma*acc/denom + x ----
    {
        int tx = tid & 15, ty = tid >> 4;
        float* sT = sKV;                           // [64][17] = 1088 <= 8704
        float vv[4] = {o0, o1, o2, o3};
#pragma unroll
        for (int j = 0; j < 4; j++)
            sT[((tx << 2) + j) * 17 + ty] = vv[j];
        __syncthreads();
        float g = *gamma_p;
#pragma unroll
        for (int it = 0; it < 4; it++) {
            int idx = it * 256 + tid;
            int d = idx >> 4, q = idx & 15;
            int gi = (h * HD + d) * HW + q0 + q;
            out[gi] = g * sT[d * 17 + q] * sInv[q] + x[gi];
        }
    }
}

// ---------------------------------------------------------------------------
extern "C" void kernel_launch(void* const* d_in, const int* in_sizes, int n_in,
                              void* d_out, int out_size) {
    const float* x     = (const float*)d_in[0];
    const float* Wq    = (const float*)d_in[1];
    const float* bq    = (const float*)d_in[2];
    const float* Wk    = (const float*)d_in[3];
    const float* bk    = (const float*)d_in[4];
    const float* Wv    = (const float*)d_in[5];
    const float* bv    = (const float*)d_in[6];
    const float* gamma = (const float*)d_in[7];
    float* out = (float*)d_out;

    pad_kernel<<<(C_ * KP) / 256, 256>>>(x);
    gemm_all_kernel<<<328, 256>>>(Wq, bq, Wk, bk, Wv, bv, x);

    const int smem_bytes = (2048 + 8704 + 16 * SEW + 16) * 4;  // 108864
    cudaFuncSetAttribute(attn_kernel, cudaFuncAttributeMaxDynamicSharedMemorySize, smem_bytes);
    attn_kernel<<<dim3(HW / 16, NH), 256, smem_bytes>>>(x, gamma, out);
}

// round 5
// speedup vs baseline: 1.3274x; 1.3274x over previous
#include <cuda_runtime.h>

#define C_  512
#define Hh  24
#define Ww  24
#define HW  576
#define NH  8
#define HD  64
#define PW  30
#define PP  900
#define KP  960
#define SE_STRIDE 968

typedef unsigned long long ull;

// Scratch (device globals: allocation-free)
__device__ float g_Xp[C_ * KP];   // reflect-padded x, keys padded to 960 (zeros)
__device__ float g_Q [C_ * HW];   // Q[o][p]
__device__ float g_K [C_ * KP];   // K[o][pp]
__device__ float g_VT[KP * C_];   // V transposed: VT[pp][o]

// ---- packed fp32x2 helpers ----
__device__ __forceinline__ void fma2(ull &d, ull a, ull b) {
    asm("fma.rn.f32x2 %0, %1, %2, %0;" : "+l"(d) : "l"(a), "l"(b));
}
__device__ __forceinline__ ull pk2(float x, float y) {
    ull r; asm("mov.b64 %0, {%1, %2};" : "=l"(r) : "f"(x), "f"(y)); return r;
}
__device__ __forceinline__ float2 upk(ull v) {
    float2 r; asm("mov.b64 {%0, %1}, %2;" : "=f"(r.x), "=f"(r.y) : "l"(v)); return r;
}

// ---------------------------------------------------------------------------
// Kernel 1: reflect-pad gather. g_Xp[c][pp] (pp = pr*30+pc), zeros for pp>=900.
// ---------------------------------------------------------------------------
__global__ void pad_kernel(const float* __restrict__ x) {
    int idx = blockIdx.x * 256 + threadIdx.x;
    if (idx >= C_ * KP) return;
    int c = idx / KP, pp = idx - c * KP;
    float v = 0.f;
    if (pp < PP) {
        int pr = pp / PW, pc = pp - pr * PW;
        int r = pr - 3; r = (r < 0) ? -r : ((r >= Hh) ? 2 * Hh - 2 - r : r);
        int cl = pc - 3; cl = (cl < 0) ? -cl : ((cl >= Ww) ? 2 * Ww - 2 - cl : cl);
        v = x[c * HW + r * Ww + cl];
    }
    g_Xp[idx] = v;
}

// ---------------------------------------------------------------------------
// Kernel 2 (fused): all three conv1x1 GEMMs, 312 CTAs x 128 threads.
//   bid [0,72)   : Q  = Wq @ x      (N=576)
//   bid [72,192) : K  = Wk @ Xp     (N=960)
//   bid [192,312): VT = (Wv @ Xp)^T (N=960, transposed store via smem)
// 64x64 tile, 4o x 8n micro-tile (16 FFMA2/step, 16 accumulators),
// double-buffered smem, one sync per 16-deep c-chunk.
// Inner t-step: 3 LDS + ~8 MOV + 16 FFMA2 = 27 issues / 32 fma-pipe cycles.
// ---------------------------------------------------------------------------
__global__ void __launch_bounds__(128) gemm_all_kernel(
    const float* __restrict__ Wq, const float* __restrict__ bq,
    const float* __restrict__ Wk, const float* __restrict__ bk,
    const float* __restrict__ Wv, const float* __restrict__ bv,
    const float* __restrict__ x)
{
    __shared__ float sm[4224];  // sA0@0[1088] sA1@1088[1088] sB0@2176[1024] sB1@3200[1024]

    int bid = blockIdx.x;
    const float *Wm, *bias, *X; float* Cout; int N, transp = 0, nt, ot;
    if (bid < 72)       { nt = bid % 9;       ot = bid / 9;       Wm = Wq; bias = bq; X = x;    Cout = g_Q;  N = HW; }
    else if (bid < 192) { int b = bid - 72;   nt = b % 15; ot = b / 15; Wm = Wk; bias = bk; X = g_Xp; Cout = g_K;  N = KP; }
    else                { int b = bid - 192;  nt = b % 15; ot = b / 15; Wm = Wv; bias = bv; X = g_Xp; Cout = g_VT; N = KP; transp = 1; }
    int nB = nt * 64, oB = ot * 64;

    int tid = threadIdx.x;
    int tj = tid & 7, ti = tid >> 3;             // micro-tile: 4 o-rows (4ti), 8 n-cols (8tj)
    int aoo = tid & 63, acg = (tid >> 6) << 3;   // A stage: o-row, c-group of 8
    int bl = tid >> 3, bn = (tid & 7) << 3;      // B stage: c-row 0..15, n-group of 8

    float* sA[2] = { sm,        sm + 1088 };     // [c][o], stride 68
    float* sB[2] = { sm + 2176, sm + 3200 };     // [c][n], stride 64

    ull acc[4][4];
#pragma unroll
    for (int i = 0; i < 4; i++)
#pragma unroll
        for (int j = 0; j < 4; j++) acc[i][j] = 0ULL;

    // preload chunk 0
    {
        float4 w0 = *(const float4*)&Wm[(oB + aoo) * C_ + acg];
        float4 w1 = *(const float4*)&Wm[(oB + aoo) * C_ + acg + 4];
        float4 x0 = *(const float4*)&X[bl * N + nB + bn];
        float4 x1 = *(const float4*)&X[bl * N + nB + bn + 4];
        float wv[8] = {w0.x, w0.y, w0.z, w0.w, w1.x, w1.y, w1.z, w1.w};
#pragma unroll
        for (int j = 0; j < 8; j++) sA[0][(acg + j) * 68 + aoo] = wv[j];
        *(float4*)&sB[0][bl * 64 + bn]     = x0;
        *(float4*)&sB[0][bl * 64 + bn + 4] = x1;
    }
    __syncthreads();

    for (int cc = 0; cc < C_; cc += 16) {
        int cur = (cc >> 4) & 1;
        const float* cA = sA[cur];
        const float* cB = sB[cur];
        bool pf = cc + 16 < C_;
        float4 w0n, w1n, x0n, x1n;
        if (pf) {
            w0n = *(const float4*)&Wm[(oB + aoo) * C_ + cc + 16 + acg];
            w1n = *(const float4*)&Wm[(oB + aoo) * C_ + cc + 16 + acg + 4];
            x0n = *(const float4*)&X[(cc + 16 + bl) * N + nB + bn];
            x1n = *(const float4*)&X[(cc + 16 + bl) * N + nB + bn + 4];
        }
#pragma unroll
        for (int t = 0; t < 16; t++) {
            float4 a4 = *(const float4*)&cA[t * 68 + (ti << 2)];
            ulonglong2 b0 = *(const ulonglong2*)&cB[t * 64 + (tj << 3)];
            ulonglong2 b1 = *(const ulonglong2*)&cB[t * 64 + (tj << 3) + 4];
            ull d0 = pk2(a4.x, a4.x);
            ull d1 = pk2(a4.y, a4.y);
            ull d2 = pk2(a4.z, a4.z);
            ull d3 = pk2(a4.w, a4.w);
            fma2(acc[0][0], d0, b0.x); fma2(acc[0][1], d0, b0.y);
            fma2(acc[0][2], d0, b1.x); fma2(acc[0][3], d0, b1.y);
            fma2(acc[1][0], d1, b0.x); fma2(acc[1][1], d1, b0.y);
            fma2(acc[1][2], d1, b1.x); fma2(acc[1][3], d1, b1.y);
            fma2(acc[2][0], d2, b0.x); fma2(acc[2][1], d2, b0.y);
            fma2(acc[2][2], d2, b1.x); fma2(acc[2][3], d2, b1.y);
            fma2(acc[3][0], d3, b0.x); fma2(acc[3][1], d3, b0.y);
            fma2(acc[3][2], d3, b1.x); fma2(acc[3][3], d3, b1.y);
        }
        if (pf) {
            float* nA = sA[cur ^ 1];
            float* nBp = sB[cur ^ 1];
            float wv[8] = {w0n.x, w0n.y, w0n.z, w0n.w, w1n.x, w1n.y, w1n.z, w1n.w};
#pragma unroll
            for (int j = 0; j < 8; j++) nA[(acg + j) * 68 + aoo] = wv[j];
            *(float4*)&nBp[bl * 64 + bn]     = x0n;
            *(float4*)&nBp[bl * 64 + bn + 4] = x1n;
        }
        __syncthreads();
    }

    // epilogue: each thread owns rows oB+4ti..+3, cols nB+8tj..+7
    float4 lo[4], hi[4];
#pragma unroll
    for (int i = 0; i < 4; i++) {
        float bv_ = bias[oB + (ti << 2) + i];
        float2 c0 = upk(acc[i][0]), c1 = upk(acc[i][1]);
        float2 c2 = upk(acc[i][2]), c3 = upk(acc[i][3]);
        lo[i] = make_float4(c0.x + bv_, c0.y + bv_, c1.x + bv_, c1.y + bv_);
        hi[i] = make_float4(c2.x + bv_, c2.y + bv_, c3.x + bv_, c3.y + bv_);
    }
    if (!transp) {
#pragma unroll
        for (int i = 0; i < 4; i++) {
            int o = oB + (ti << 2) + i;
            *(float4*)&Cout[o * N + nB + (tj << 3)]     = lo[i];
            *(float4*)&Cout[o * N + nB + (tj << 3) + 4] = hi[i];
        }
    } else {
        // transpose through smem for coalesced VT stores (sm free: loop ended in sync)
        float* sT = sm;                          // [n][o], 64 x 65 = 4160 <= 4224
#pragma unroll
        for (int i = 0; i < 4; i++) {
            int o = (ti << 2) + i;
            float lv[4] = {lo[i].x, lo[i].y, lo[i].z, lo[i].w};
            float hv[4] = {hi[i].x, hi[i].y, hi[i].z, hi[i].w};
#pragma unroll
            for (int j = 0; j < 4; j++) {
                sT[((tj << 3) + j) * 65 + o]     = lv[j];
                sT[((tj << 3) + 4 + j) * 65 + o] = hv[j];
            }
        }
        __syncthreads();
#pragma unroll
        for (int it = 0; it < 32; it++) {
            int idx = it * 128 + tid;
            int n = idx >> 6, o = idx & 63;
            Cout[(nB + n) * C_ + oB + o] = sT[n * 65 + o];
        }
    }
}

// ---------------------------------------------------------------------------
// Kernel 3: fused attention over 960 (padded) deduplicated keys with
// multiplicity-weighted softmax. Grid (18 qtiles, 8 heads) = 144 CTAs.
// Double-buffered K/V staging; full 32x960 E tile in smem.  (R2 verbatim)
// ---------------------------------------------------------------------------
__global__ void __launch_bounds__(256) attn_kernel(const float* __restrict__ x,
                            const float* __restrict__ gamma_p,
                            float* __restrict__ out) {
    extern __shared__ float sm[];
    float* sQ   = sm;                      // 64*32  = 2048 : sQ[d][q]
    float* sKV0 = sm + 2048;               // 64*68  = 4352
    float* sKV1 = sKV0 + 4352;             // 64*68  = 4352
    float* sE   = sKV1 + 4352;             // 32*968 = 30976
    float* sInv = sE + 32 * SE_STRIDE;     // 32

    int h   = blockIdx.y;
    int q0  = blockIdx.x * 32;
    int tid = threadIdx.x;
    int tx  = tid & 15, ty = tid >> 4;
    int tx4 = tx << 2;
    int dstg = tid >> 2, cstg = (tid & 3) << 4;
    float* sKVb[2] = { sKV0, sKV1 };

    // Load Q tile (d-major), vectorized
    for (int i = tid; i < 64 * 8; i += 256) {
        int d = i >> 3, qg = (i & 7) << 2;
        *(float4*)&sQ[d * 32 + qg] = *(const float4*)&g_Q[(h * HD + d) * HW + q0 + qg];
    }
    // preload K chunk 0
    {
        const float4* src = (const float4*)&g_K[(h * HD + dstg) * KP + cstg];
        float4 r0 = src[0], r1 = src[1], r2 = src[2], r3 = src[3];
        float4* dst = (float4*)&sKV0[dstg * 68 + cstg];
        dst[0] = r0; dst[1] = r1; dst[2] = r2; dst[3] = r3;
    }
    __syncthreads();

    // ---- Pass 1: E[q][k] = sum_d Q[d][q] * K[d][k] ----
    for (int kc = 0; kc < KP; kc += 64) {
        int cur = (kc >> 6) & 1;
        const float* cKV = sKVb[cur];
        bool pf = kc + 64 < KP;
        float4 r0, r1, r2, r3;
        if (pf) {
            const float4* src = (const float4*)&g_K[(h * HD + dstg) * KP + kc + 64 + cstg];
            r0 = src[0]; r1 = src[1]; r2 = src[2]; r3 = src[3];
        }
        ull e00 = 0, e01 = 0, e10 = 0, e11 = 0;
#pragma unroll 16
        for (int d = 0; d < 64; d++) {
            float2 a = *(const float2*)&sQ[d * 32 + (ty << 1)];
            float4 b = *(const float4*)&cKV[d * 68 + tx4];
            ull b01 = pk2(b.x, b.y), b23 = pk2(b.z, b.w);
            ull a0 = pk2(a.x, a.x), a1 = pk2(a.y, a.y);
            fma2(e00, a0, b01); fma2(e01, a0, b23);
            fma2(e10, a1, b01); fma2(e11, a1, b23);
        }
        {
            float2 p0 = upk(e00), p1 = upk(e01), p2 = upk(e10), p3 = upk(e11);
            int r = (ty << 1) * SE_STRIDE + kc + tx4;
            *(float4*)&sE[r]             = make_float4(p0.x, p0.y, p1.x, p1.y);
            *(float4*)&sE[r + SE_STRIDE] = make_float4(p2.x, p2.y, p3.x, p3.y);
        }
        if (pf) {
            float4* dst = (float4*)&sKVb[cur ^ 1][dstg * 68 + cstg];
            dst[0] = r0; dst[1] = r1; dst[2] = r2; dst[3] = r3;
        }
        __syncthreads();
    }

    // issue V chunk-0 global loads early; they complete under softmax
    float4 v0r, v1r, v2r, v3r;
    {
        const float4* src = (const float4*)&g_VT[dstg * C_ + h * HD + cstg];
        v0r = src[0]; v1r = src[1]; v2r = src[2]; v3r = src[3];
    }

    // ---- Multiplicity-weighted softmax, in place: P = mult*exp(E-max) ----
    {
        int row = tid >> 3, part = tid & 7;      // 8 threads per query row
        float* Er = &sE[row * SE_STRIDE];
        int i0 = part * 120;
        float m = -1e30f;
        for (int i = i0; i < i0 + 120; i++) m = fmaxf(m, Er[i]);
        m = fmaxf(m, __shfl_xor_sync(~0u, m, 1));
        m = fmaxf(m, __shfl_xor_sync(~0u, m, 2));
        m = fmaxf(m, __shfl_xor_sync(~0u, m, 4));
        float s = 0.f;
        for (int i = i0; i < i0 + 120; i++) {
            float w = 0.f;
            if (i < PP) {
                int pr = i / PW, pc = i - pr * PW;
                int mr = min(pr + 1, min(7, PW - pr));
                int mc = min(pc + 1, min(7, PW - pc));
                w = (float)(mr * mc);
            }
            float p = w * __expf(Er[i] - m);
            Er[i] = p;
            s += p;
        }
        s += __shfl_xor_sync(~0u, s, 1);
        s += __shfl_xor_sync(~0u, s, 2);
        s += __shfl_xor_sync(~0u, s, 4);
        if (part == 0) sInv[row] = 1.f / s;
    }
    // store V chunk 0 (pass 1 / softmax no longer touch sKV0)
    {
        float4* dst = (float4*)&sKV0[dstg * 68 + cstg];
        dst[0] = v0r; dst[1] = v1r; dst[2] = v2r; dst[3] = v3r;
    }
    __syncthreads();

    // ---- Pass 2: out[q][d] = sum_k P[q][k] * VT[k][d] ----
    ull o00 = 0, o01 = 0, o10 = 0, o11 = 0;
    for (int kc = 0; kc < KP; kc += 64) {
        int cur = (kc >> 6) & 1;
        const float* cKV = sKVb[cur];
        bool pf = kc + 64 < KP;
        float4 r0, r1, r2, r3;
        if (pf) {
            const float4* src = (const float4*)&g_VT[(kc + 64 + dstg) * C_ + h * HD + cstg];
            r0 = src[0]; r1 = src[1]; r2 = src[2]; r3 = src[3];
        }
        const float* sEr0 = &sE[(ty << 1) * SE_STRIDE + kc];
        const float* sEr1 = sEr0 + SE_STRIDE;
#pragma unroll 8
        for (int k = 0; k < 64; k += 2) {
            float2 pa = *(const float2*)&sEr0[k];
            float2 pb = *(const float2*)&sEr1[k];
            float4 va = *(const float4*)&cKV[k * 68 + tx4];
            float4 vb = *(const float4*)&cKV[(k + 1) * 68 + tx4];
            ull va01 = pk2(va.x, va.y), va23 = pk2(va.z, va.w);
            ull vb01 = pk2(vb.x, vb.y), vb23 = pk2(vb.z, vb.w);
            ull pax = pk2(pa.x, pa.x), pbx = pk2(pb.x, pb.x);
            ull pay = pk2(pa.y, pa.y), pby = pk2(pb.y, pb.y);
            fma2(o00, pax, va01); fma2(o01, pax, va23);
            fma2(o10, pbx, va01); fma2(o11, pbx, va23);
            fma2(o00, pay, vb01); fma2(o01, pay, vb23);
            fma2(o10, pby, vb01); fma2(o11, pby, vb23);
        }
        if (pf) {
            float4* dst = (float4*)&sKVb[cur ^ 1][dstg * 68 + cstg];
            dst[0] = r0; dst[1] = r1; dst[2] = r2; dst[3] = r3;
        }
        __syncthreads();
    }

    // ---- Epilogue via smem transpose: out = gamma*acc/denom + x, coalesced ----
    {
        float2 a0 = upk(o00), a1 = upk(o01), a2 = upk(o10), a3 = upk(o11);
        float v0[4] = {a0.x, a0.y, a1.x, a1.y};
        float v1[4] = {a2.x, a2.y, a3.x, a3.y};
        float* sOut = sKV0;                       // 64 x 33 <= 4352, loop-end sync passed
        int qr = ty << 1;
#pragma unroll
        for (int j = 0; j < 4; j++) {
            sOut[(tx4 + j) * 33 + qr]     = v0[j];
            sOut[(tx4 + j) * 33 + qr + 1] = v1[j];
        }
        __syncthreads();
        float g = *gamma_p;
        for (int i = tid; i < 64 * 32; i += 256) {
            int d = i >> 5, q = i & 31;
            int gi = (h * HD + d) * HW + q0 + q;
            out[gi] = g * sOut[d * 33 + q] * sInv[q] + x[gi];
        }
    }
}

// ---------------------------------------------------------------------------
extern "C" void kernel_launch(void* const* d_in, const int* in_sizes, int n_in,
                              void* d_out, int out_size) {
    const float* x     = (const float*)d_in[0];
    const float* Wq    = (const float*)d_in[1];
    const float* bq    = (const float*)d_in[2];
    const float* Wk    = (const float*)d_in[3];
    const float* bk    = (const float*)d_in[4];
    const float* Wv    = (const float*)d_in[5];
    const float* bv    = (const float*)d_in[6];
    const float* gamma = (const float*)d_in[7];
    float* out = (float*)d_out;

    pad_kernel<<<(C_ * KP + 255) / 256, 256>>>(x);
    gemm_all_kernel<<<312, 128>>>(Wq, bq, Wk, bk, Wv, bv, x);

    const int smem_bytes = (2048 + 2 * 4352 + 32 * SE_STRIDE + 32) * 4;  // 167040
    cudaFuncSetAttribute(attn_kernel, cudaFuncAttributeMaxDynamicSharedMemorySize, smem_bytes);
    attn_kernel<<<dim3(HW / 32, NH), 256, smem_bytes>>>(x, gamma, out);
}

// round 6
// speedup vs baseline: 1.9782x; 1.4902x over previous
#include <cuda_runtime.h>
#include <cstdint>

#define C_  512
#define Hh  24
#define Ww  24
#define HW  576
#define NH  8
#define HD  64
#define PW  30
#define PP  900
#define KP  960
#define SE_STRIDE 968

typedef unsigned long long ull;

// Scratch (device globals: allocation-free)
__device__ float g_Xp[C_ * KP];   // reflect-padded x, keys padded to 960 (zeros)
__device__ float g_Q [C_ * HW];   // Q[o][p]
__device__ float g_K [C_ * KP];   // K[o][pp]
__device__ float g_VT[KP * C_];   // V transposed: VT[pp][o]

// ---- packed fp32x2 helpers (attention kernel) ----
__device__ __forceinline__ void fma2(ull &d, ull a, ull b) {
    asm("fma.rn.f32x2 %0, %1, %2, %0;" : "+l"(d) : "l"(a), "l"(b));
}
__device__ __forceinline__ ull pk2(float x, float y) {
    ull r; asm("mov.b64 %0, {%1, %2};" : "=l"(r) : "f"(x), "f"(y)); return r;
}
__device__ __forceinline__ float2 upk(ull v) {
    float2 r; asm("mov.b64 {%0, %1}, %2;" : "=f"(r.x), "=f"(r.y) : "l"(v)); return r;
}

// ---- tf32 tensor-core helpers ----
__device__ __forceinline__ uint32_t f2tf(float f) {
    uint32_t r; asm("cvt.rna.tf32.f32 %0, %1;" : "=r"(r) : "f"(f)); return r;
}
__device__ __forceinline__ void mma_tf32(float* c, const uint32_t* a, const uint32_t* b) {
    asm("mma.sync.aligned.m16n8k8.row.col.f32.tf32.tf32.f32 "
        "{%0,%1,%2,%3}, {%4,%5,%6,%7}, {%8,%9}, {%0,%1,%2,%3};"
        : "+f"(c[0]), "+f"(c[1]), "+f"(c[2]), "+f"(c[3])
        : "r"(a[0]), "r"(a[1]), "r"(a[2]), "r"(a[3]), "r"(b[0]), "r"(b[1]));
}

// ---------------------------------------------------------------------------
// Kernel 1: reflect-pad gather. g_Xp[c][pp] (pp = pr*30+pc), zeros for pp>=900.
// ---------------------------------------------------------------------------
__global__ void pad_kernel(const float* __restrict__ x) {
    int idx = blockIdx.x * 256 + threadIdx.x;
    if (idx >= C_ * KP) return;
    int c = idx / KP, pp = idx - c * KP;
    float v = 0.f;
    if (pp < PP) {
        int pr = pp / PW, pc = pp - pr * PW;
        int r = pr - 3; r = (r < 0) ? -r : ((r >= Hh) ? 2 * Hh - 2 - r : r);
        int cl = pc - 3; cl = (cl < 0) ? -cl : ((cl >= Ww) ? 2 * Ww - 2 - cl : cl);
        v = x[c * HW + r * Ww + cl];
    }
    g_Xp[idx] = v;
}

// ---------------------------------------------------------------------------
// Kernel 2 (fused): all three conv1x1 GEMMs via mma.sync tf32. 312 CTAs x 128.
//   bid [0,72)   : Q  = Wq @ x      (N=576)
//   bid [72,192) : K  = Wk @ Xp     (N=960)
//   bid [192,312): VT = (Wv @ Xp)^T (N=960, transposed store via smem)
// CTA tile 64o x 64n, 4 warps (2x2), warp tile 32x32 (2 msub x 4 nsub m16n8k8).
// k-chunks of 32, double-buffered; tf32 conversion at staging (once/element).
// Fragment LDS strides 36 (A) / 72 (B) -> conflict-free loads.
// ---------------------------------------------------------------------------
__global__ void __launch_bounds__(128) gemm_all_kernel(
    const float* __restrict__ Wq, const float* __restrict__ bq,
    const float* __restrict__ Wk, const float* __restrict__ bk,
    const float* __restrict__ Wv, const float* __restrict__ bv,
    const float* __restrict__ x)
{
    __shared__ uint32_t smu[9216];   // sA0[2304] sA1[2304] sB0[2304] sB1[2304] = 36KB
    uint32_t* sA[2] = { smu,        smu + 2304 };   // [o][k] tf32, stride 36
    uint32_t* sB[2] = { smu + 4608, smu + 6912 };   // [k][n] tf32, stride 72

    int bid = blockIdx.x;
    const float *Wm, *bias, *X; float* Cout; int N, transp = 0, nt, ot;
    if (bid < 72)       { nt = bid % 9;      ot = bid / 9;       Wm = Wq; bias = bq; X = x;    Cout = g_Q;  N = HW; }
    else if (bid < 192) { int b = bid - 72;  nt = b % 15; ot = b / 15; Wm = Wk; bias = bk; X = g_Xp; Cout = g_K;  N = KP; }
    else                { int b = bid - 192; nt = b % 15; ot = b / 15; Wm = Wv; bias = bv; X = g_Xp; Cout = g_VT; N = KP; transp = 1; }
    int nB = nt * 64, oB = ot * 64;

    int tid  = threadIdx.x;
    int lane = tid & 31, wid = tid >> 5;
    int warp_m = wid & 1, warp_n = wid >> 1;     // 2x2 warps
    int grp = lane >> 2, qd = lane & 3;

    // staging thread mapping
    int arow = tid >> 1, ahalf = (tid & 1) << 4;     // A: 64 rows x 2 halves of 16
    int brow = tid >> 2, boff  = (tid & 3) << 4;     // B: 32 rows x 4 groups of 16

    float acc[2][4][4];
#pragma unroll
    for (int i = 0; i < 2; i++)
#pragma unroll
        for (int j = 0; j < 4; j++)
#pragma unroll
            for (int e = 0; e < 4; e++) acc[i][j][e] = 0.f;

    // ---- stage chunk 0 ----
    {
        const float4* aS = (const float4*)&Wm[(oB + arow) * C_ + ahalf];
        const float4* bS = (const float4*)&X[brow * N + nB + boff];
#pragma unroll
        for (int g = 0; g < 4; g++) {
            float4 w = aS[g];
            uint4 t = make_uint4(f2tf(w.x), f2tf(w.y), f2tf(w.z), f2tf(w.w));
            *(uint4*)&sA[0][arow * 36 + ahalf + 4 * g] = t;
        }
#pragma unroll
        for (int g = 0; g < 4; g++) {
            float4 v = bS[g];
            uint4 t = make_uint4(f2tf(v.x), f2tf(v.y), f2tf(v.z), f2tf(v.w));
            *(uint4*)&sB[0][brow * 72 + boff + 4 * g] = t;
        }
    }
    __syncthreads();

    int buf = 0;
    for (int cc = 0; cc < C_; cc += 32) {
        bool pf = cc + 32 < C_;
        float4 wreg[4], xreg[4];
        if (pf) {
            const float4* aS = (const float4*)&Wm[(oB + arow) * C_ + cc + 32 + ahalf];
            const float4* bS = (const float4*)&X[(cc + 32 + brow) * N + nB + boff];
#pragma unroll
            for (int g = 0; g < 4; g++) wreg[g] = aS[g];
#pragma unroll
            for (int g = 0; g < 4; g++) xreg[g] = bS[g];
        }
        const uint32_t* cA = sA[buf];
        const uint32_t* cB = sB[buf];
#pragma unroll
        for (int ks = 0; ks < 4; ks++) {
            int kb = ks << 3;
            uint32_t afr[2][4];
#pragma unroll
            for (int ms = 0; ms < 2; ms++) {
                int base = warp_m * 32 + ms * 16 + grp;
                afr[ms][0] = cA[(base    ) * 36 + kb + qd];
                afr[ms][1] = cA[(base + 8) * 36 + kb + qd];
                afr[ms][2] = cA[(base    ) * 36 + kb + 4 + qd];
                afr[ms][3] = cA[(base + 8) * 36 + kb + 4 + qd];
            }
            uint32_t bfr[4][2];
#pragma unroll
            for (int ns = 0; ns < 4; ns++) {
                int n = warp_n * 32 + ns * 8 + grp;
                bfr[ns][0] = cB[(kb + qd    ) * 72 + n];
                bfr[ns][1] = cB[(kb + 4 + qd) * 72 + n];
            }
#pragma unroll
            for (int ms = 0; ms < 2; ms++)
#pragma unroll
                for (int ns = 0; ns < 4; ns++)
                    mma_tf32(acc[ms][ns], afr[ms], bfr[ns]);
        }
        if (pf) {
            uint32_t* nA = sA[buf ^ 1];
            uint32_t* nBp = sB[buf ^ 1];
#pragma unroll
            for (int g = 0; g < 4; g++) {
                float4 w = wreg[g];
                uint4 t = make_uint4(f2tf(w.x), f2tf(w.y), f2tf(w.z), f2tf(w.w));
                *(uint4*)&nA[arow * 36 + ahalf + 4 * g] = t;
            }
#pragma unroll
            for (int g = 0; g < 4; g++) {
                float4 v = xreg[g];
                uint4 t = make_uint4(f2tf(v.x), f2tf(v.y), f2tf(v.z), f2tf(v.w));
                *(uint4*)&nBp[brow * 72 + boff + 4 * g] = t;
            }
        }
        __syncthreads();
        buf ^= 1;
    }

    // ---- epilogue ----
    if (!transp) {
#pragma unroll
        for (int ms = 0; ms < 2; ms++)
#pragma unroll
            for (int part = 0; part < 2; part++) {
                int row = warp_m * 32 + ms * 16 + grp + part * 8;
                float bv_ = bias[oB + row];
#pragma unroll
                for (int ns = 0; ns < 4; ns++) {
                    float2 val = make_float2(acc[ms][ns][2 * part] + bv_,
                                             acc[ms][ns][2 * part + 1] + bv_);
                    *(float2*)&Cout[(oB + row) * N + nB + warp_n * 32 + ns * 8 + 2 * qd] = val;
                }
            }
    } else {
        float* sT = (float*)smu;                 // [n][o], 64 x 65 = 4160 <= 9216
#pragma unroll
        for (int ms = 0; ms < 2; ms++)
#pragma unroll
            for (int part = 0; part < 2; part++) {
                int row = warp_m * 32 + ms * 16 + grp + part * 8;
                float bv_ = bias[oB + row];
#pragma unroll
                for (int ns = 0; ns < 4; ns++) {
                    int n = warp_n * 32 + ns * 8 + 2 * qd;
                    sT[(n    ) * 65 + row] = acc[ms][ns][2 * part] + bv_;
                    sT[(n + 1) * 65 + row] = acc[ms][ns][2 * part + 1] + bv_;
                }
            }
        __syncthreads();
#pragma unroll
        for (int it = 0; it < 32; it++) {
            int idx = it * 128 + tid;
            int n = idx >> 6, o = idx & 63;
            Cout[(nB + n) * C_ + oB + o] = sT[n * 65 + o];
        }
    }
}

// ---------------------------------------------------------------------------
// Kernel 3: fused attention over 960 (padded) deduplicated keys with
// multiplicity-weighted softmax. Grid (18 qtiles, 8 heads) = 144 CTAs.
// Double-buffered K/V staging; full 32x960 E tile in smem.  (R2 verbatim)
// ---------------------------------------------------------------------------
__global__ void __launch_bounds__(256) attn_kernel(const float* __restrict__ x,
                            const float* __restrict__ gamma_p,
                            float* __restrict__ out) {
    extern __shared__ float sm[];
    float* sQ   = sm;                      // 64*32  = 2048 : sQ[d][q]
    float* sKV0 = sm + 2048;               // 64*68  = 4352
    float* sKV1 = sKV0 + 4352;             // 64*68  = 4352
    float* sE   = sKV1 + 4352;             // 32*968 = 30976
    float* sInv = sE + 32 * SE_STRIDE;     // 32

    int h   = blockIdx.y;
    int q0  = blockIdx.x * 32;
    int tid = threadIdx.x;
    int tx  = tid & 15, ty = tid >> 4;
    int tx4 = tx << 2;
    int dstg = tid >> 2, cstg = (tid & 3) << 4;
    float* sKVb[2] = { sKV0, sKV1 };

    // Load Q tile (d-major), vectorized
    for (int i = tid; i < 64 * 8; i += 256) {
        int d = i >> 3, qg = (i & 7) << 2;
        *(float4*)&sQ[d * 32 + qg] = *(const float4*)&g_Q[(h * HD + d) * HW + q0 + qg];
    }
    // preload K chunk 0
    {
        const float4* src = (const float4*)&g_K[(h * HD + dstg) * KP + cstg];
        float4 r0 = src[0], r1 = src[1], r2 = src[2], r3 = src[3];
        float4* dst = (float4*)&sKV0[dstg * 68 + cstg];
        dst[0] = r0; dst[1] = r1; dst[2] = r2; dst[3] = r3;
    }
    __syncthreads();

    // ---- Pass 1: E[q][k] = sum_d Q[d][q] * K[d][k] ----
    for (int kc = 0; kc < KP; kc += 64) {
        int cur = (kc >> 6) & 1;
        const float* cKV = sKVb[cur];
        bool pf = kc + 64 < KP;
        float4 r0, r1, r2, r3;
        if (pf) {
            const float4* src = (const float4*)&g_K[(h * HD + dstg) * KP + kc + 64 + cstg];
            r0 = src[0]; r1 = src[1]; r2 = src[2]; r3 = src[3];
        }
        ull e00 = 0, e01 = 0, e10 = 0, e11 = 0;
#pragma unroll 16
        for (int d = 0; d < 64; d++) {
            float2 a = *(const float2*)&sQ[d * 32 + (ty << 1)];
            float4 b = *(const float4*)&cKV[d * 68 + tx4];
            ull b01 = pk2(b.x, b.y), b23 = pk2(b.z, b.w);
            ull a0 = pk2(a.x, a.x), a1 = pk2(a.y, a.y);
            fma2(e00, a0, b01); fma2(e01, a0, b23);
            fma2(e10, a1, b01); fma2(e11, a1, b23);
        }
        {
            float2 p0 = upk(e00), p1 = upk(e01), p2 = upk(e10), p3 = upk(e11);
            int r = (ty << 1) * SE_STRIDE + kc + tx4;
            *(float4*)&sE[r]             = make_float4(p0.x, p0.y, p1.x, p1.y);
            *(float4*)&sE[r + SE_STRIDE] = make_float4(p2.x, p2.y, p3.x, p3.y);
        }
        if (pf) {
            float4* dst = (float4*)&sKVb[cur ^ 1][dstg * 68 + cstg];
            dst[0] = r0; dst[1] = r1; dst[2] = r2; dst[3] = r3;
        }
        __syncthreads();
    }

    // issue V chunk-0 global loads early; they complete under softmax
    float4 v0r, v1r, v2r, v3r;
    {
        const float4* src = (const float4*)&g_VT[dstg * C_ + h * HD + cstg];
        v0r = src[0]; v1r = src[1]; v2r = src[2]; v3r = src[3];
    }

    // ---- Multiplicity-weighted softmax, in place: P = mult*exp(E-max) ----
    {
        int row = tid >> 3, part = tid & 7;      // 8 threads per query row
        float* Er = &sE[row * SE_STRIDE];
        int i0 = part * 120;
        float m = -1e30f;
        for (int i = i0; i < i0 + 120; i++) m = fmaxf(m, Er[i]);
        m = fmaxf(m, __shfl_xor_sync(~0u, m, 1));
        m = fmaxf(m, __shfl_xor_sync(~0u, m, 2));
        m = fmaxf(m, __shfl_xor_sync(~0u, m, 4));
        float s = 0.f;
        for (int i = i0; i < i0 + 120; i++) {
            float w = 0.f;
            if (i < PP) {
                int pr = i / PW, pc = i - pr * PW;
                int mr = min(pr + 1, min(7, PW - pr));
                int mc = min(pc + 1, min(7, PW - pc));
                w = (float)(mr * mc);
            }
            float p = w * __expf(Er[i] - m);
            Er[i] = p;
            s += p;
        }
        s += __shfl_xor_sync(~0u, s, 1);
        s += __shfl_xor_sync(~0u, s, 2);
        s += __shfl_xor_sync(~0u, s, 4);
        if (part == 0) sInv[row] = 1.f / s;
    }
    // store V chunk 0 (pass 1 / softmax no longer touch sKV0)
    {
        float4* dst = (float4*)&sKV0[dstg * 68 + cstg];
        dst[0] = v0r; dst[1] = v1r; dst[2] = v2r; dst[3] = v3r;
    }
    __syncthreads();

    // ---- Pass 2: out[q][d] = sum_k P[q][k] * VT[k][d] ----
    ull o00 = 0, o01 = 0, o10 = 0, o11 = 0;
    for (int kc = 0; kc < KP; kc += 64) {
        int cur = (kc >> 6) & 1;
        const float* cKV = sKVb[cur];
        bool pf = kc + 64 < KP;
        float4 r0, r1, r2, r3;
        if (pf) {
            const float4* src = (const float4*)&g_VT[(kc + 64 + dstg) * C_ + h * HD + cstg];
            r0 = src[0]; r1 = src[1]; r2 = src[2]; r3 = src[3];
        }
        const float* sEr0 = &sE[(ty << 1) * SE_STRIDE + kc];
        const float* sEr1 = sEr0 + SE_STRIDE;
#pragma unroll 8
        for (int k = 0; k < 64; k += 2) {
            float2 pa = *(const float2*)&sEr0[k];
            float2 pb = *(const float2*)&sEr1[k];
            float4 va = *(const float4*)&cKV[k * 68 + tx4];
            float4 vb = *(const float4*)&cKV[(k + 1) * 68 + tx4];
            ull va01 = pk2(va.x, va.y), va23 = pk2(va.z, va.w);
            ull vb01 = pk2(vb.x, vb.y), vb23 = pk2(vb.z, vb.w);
            ull pax = pk2(pa.x, pa.x), pbx = pk2(pb.x, pb.x);
            ull pay = pk2(pa.y, pa.y), pby = pk2(pb.y, pb.y);
            fma2(o00, pax, va01); fma2(o01, pax, va23);
            fma2(o10, pbx, va01); fma2(o11, pbx, va23);
            fma2(o00, pay, vb01); fma2(o01, pay, vb23);
            fma2(o10, pby, vb01); fma2(o11, pby, vb23);
        }
        if (pf) {
            float4* dst = (float4*)&sKVb[cur ^ 1][dstg * 68 + cstg];
            dst[0] = r0; dst[1] = r1; dst[2] = r2; dst[3] = r3;
        }
        __syncthreads();
    }

    // ---- Epilogue via smem transpose: out = gamma*acc/denom + x, coalesced ----
    {
        float2 a0 = upk(o00), a1 = upk(o01), a2 = upk(o10), a3 = upk(o11);
        float v0[4] = {a0.x, a0.y, a1.x, a1.y};
        float v1[4] = {a2.x, a2.y, a3.x, a3.y};
        float* sOut = sKV0;                       // 64 x 33 <= 4352, loop-end sync passed
        int qr = ty << 1;
#pragma unroll
        for (int j = 0; j < 4; j++) {
            sOut[(tx4 + j) * 33 + qr]     = v0[j];
            sOut[(tx4 + j) * 33 + qr + 1] = v1[j];
        }
        __syncthreads();
        float g = *gamma_p;
        for (int i = tid; i < 64 * 32; i += 256) {
            int d = i >> 5, q = i & 31;
            int gi = (h * HD + d) * HW + q0 + q;
            out[gi] = g * sOut[d * 33 + q] * sInv[q] + x[gi];
        }
    }
}

// ---------------------------------------------------------------------------
extern "C" void kernel_launch(void* const* d_in, const int* in_sizes, int n_in,
                              void* d_out, int out_size) {
    const float* x     = (const float*)d_in[0];
    const float* Wq    = (const float*)d_in[1];
    const float* bq    = (const float*)d_in[2];
    const float* Wk    = (const float*)d_in[3];
    const float* bk    = (const float*)d_in[4];
    const float* Wv    = (const float*)d_in[5];
    const float* bv    = (const float*)d_in[6];
    const float* gamma = (const float*)d_in[7];
    float* out = (float*)d_out;

    pad_kernel<<<(C_ * KP + 255) / 256, 256>>>(x);
    gemm_all_kernel<<<312, 128>>>(Wq, bq, Wk, bk, Wv, bv, x);

    const int smem_bytes = (2048 + 2 * 4352 + 32 * SE_STRIDE + 32) * 4;  // 167040
    cudaFuncSetAttribute(attn_kernel, cudaFuncAttributeMaxDynamicSharedMemorySize, smem_bytes);
    attn_kernel<<<dim3(HW / 32, NH), 256, smem_bytes>>>(x, gamma, out);
}